// round 10
// baseline (speedup 1.0000x reference)
#include <cuda_runtime.h>
#include <math.h>

#define Bsz 64
#define Ssz 512
#define Hsz 400
#define Vsz 32000
#define Lsz 16
#define HC   8
#define HCW  50
#define RBLK 50            // recurrence blocks (8 H-columns each)
#define FBLK 512           // fused blocks (64 b x 8 h-chunks)
#define NBLK 562
#define NTHR 256
#define SMEM_BYTES 52000   // 13000 floats: Wt[24*400]=9600 + As[50*68]=3400

// ---------------- device globals ----------------
__device__ float g_hA[Bsz * Hsz];
__device__ float g_hB[Bsz * Hsz];
__device__ float g_x[Bsz * Hsz];
__device__ float g_xB[Lsz * Bsz * Hsz];
__device__ float g_giBT[Lsz][1200][Bsz];     // batched gi, j-major
__device__ float g_encT[Bsz][Hsz][Ssz];
__device__ float g_scpart[2][HC][Bsz][Ssz];
__device__ int   g_cnt[2][Bsz];
__device__ int   g_hCnt[Lsz],     g_hDone[Lsz];
__device__ int   g_fusedCnt[Lsz], g_fusedDone[Lsz];
__device__ int   g_batchCnt[Lsz], g_batchDone[Lsz];
__device__ int   g_bar0, g_bar0Done;

// ---------------- f32x2 helpers ----------------
__device__ __forceinline__ unsigned long long pk2(float x, float y) {
    unsigned long long r;
    asm("mov.b64 %0, {%1, %2};" : "=l"(r) : "f"(x), "f"(y));
    return r;
}
__device__ __forceinline__ void ffma2(unsigned long long& d,
                                      unsigned long long a, unsigned long long b) {
    asm("fma.rn.f32x2 %0, %1, %2, %0;" : "+l"(d) : "l"(a), "l"(b));
}
__device__ __forceinline__ float2 up2(unsigned long long v) {
    float2 f;
    asm("mov.b64 {%0, %1}, %2;" : "=f"(f.x), "=f"(f.y) : "l"(v));
    return f;
}
__device__ __forceinline__ float gru_h(float gi_r, float gh_r, float gi_z, float gh_z,
                                       float gi_n, float gh_n, float hp) {
    float r = 1.f / (1.f + expf(-(gi_r + gh_r)));
    float z = 1.f / (1.f + expf(-(gi_z + gh_z)));
    float n = tanhf(gi_n + r * gh_n);
    return (1.f - z) * n + z * hp;
}

// ---------------- sync primitives ----------------
__device__ __forceinline__ void wait_flag(int* flag) {
    if (threadIdx.x == 0) {
        int v;
        while (true) {
            asm volatile("ld.acquire.gpu.b32 %0, [%1];" : "=r"(v) : "l"(flag) : "memory");
            if (v) break;
            __nanosleep(32);
        }
    }
    __syncthreads();
}
__device__ __forceinline__ void arrive(int* cnt, int target, int* flag) {
    __threadfence();
    __syncthreads();
    if (threadIdx.x == 0) {
        int old = atomicAdd(cnt, 1);
        if (old == target - 1)
            asm volatile("st.release.gpu.b32 [%0], %1;" :: "l"(flag), "r"(1) : "memory");
    }
}

// ---------------- reset ----------------
__global__ __launch_bounds__(128) void reset_kernel() {
    int i = threadIdx.x;
    if (i < Lsz) {
        g_hCnt[i] = 0;     g_hDone[i] = 0;
        g_fusedCnt[i] = 0; g_fusedDone[i] = 0;
        g_batchCnt[i] = 0; g_batchDone[i] = 0;
    }
    if (i == 0) { g_bar0 = 0; g_bar0Done = 0; }
    if (i < Bsz) { g_cnt[0][i] = 0; g_cnt[1][i] = 0; }
}

// ---------------- persistent kernel ----------------
__global__ __launch_bounds__(NTHR, 4) void persist_kernel(
    const float* __restrict__ eh,
    const float* __restrict__ enc,
    const int* __restrict__ lens,
    const int* __restrict__ uttrs,
    const int* __restrict__ targets,
    const int* __restrict__ slot_p,
    const int* __restrict__ use_tf_p,
    const float* __restrict__ emb,
    const float* __restrict__ slot_emb,
    const float* __restrict__ Wih,
    const float* __restrict__ Whh,
    const float* __restrict__ bih,
    const float* __restrict__ bhh,
    float* __restrict__ out,
    int out_size, int write_preds)
{
    extern __shared__ float pool[];   // 13000 floats

    int bx = blockIdx.x;
    int tid = threadIdx.x;
    int gidx = bx * NTHR + tid;
    const int nt = NBLK * NTHR;

    // ============ Phase 0: zero t=0 rows + pad, init, xbuild, transpose ============
    {
        for (int i = gidx; i < Bsz * (Vsz / 4); i += nt) {
            int b = i / (Vsz / 4), q = i % (Vsz / 4);
            float4* p = (float4*)(out + (size_t)b * Lsz * Vsz) + q;
            asm volatile("st.global.cs.v4.f32 [%0], {%1, %2, %3, %4};"
                         :: "l"(p), "f"(0.f), "f"(0.f), "f"(0.f), "f"(0.f) : "memory");
        }
        for (int i = (Bsz * Lsz * Vsz) + gidx; i < out_size; i += nt)
            asm volatile("st.global.cs.f32 [%0], %1;" :: "l"(out + i), "f"(0.f) : "memory");

        int slot = slot_p[0];
        for (int i = gidx; i < Bsz * Hsz; i += nt) {
            g_hA[i] = eh[i];
            g_x[i] = slot_emb[slot * Hsz + i % Hsz];
        }
        for (int i = gidx; i < Lsz * Bsz * 100; i += nt) {
            int row = i / 100, q = i % 100;
            int t = row >> 6, b = row & 63;
            const float* src = (t == 0) ? (slot_emb + slot * Hsz)
                                        : (emb + (size_t)targets[b * Lsz + (t - 1)] * Hsz);
            ((float4*)(g_xB + (size_t)row * Hsz))[q] = ((const float4*)src)[q];
        }
        // transpose enc -> encT
        float (*tile)[33] = (float(*)[33])pool;
        int tx = tid & 31, ty = tid >> 5;   // 32 x 8
        for (int tt = bx; tt < Bsz * 16 * 13; tt += NBLK) {
            int b = tt / (16 * 13);
            int rem = tt % (16 * 13);
            int s0 = (rem / 13) * 32;
            int h0 = (rem % 13) * 32;
            __syncthreads();
            #pragma unroll
            for (int i = 0; i < 32; i += 8) {
                int s = s0 + ty + i, h = h0 + tx;
                if (h < Hsz) tile[ty + i][tx] = enc[((size_t)b * Ssz + s) * Hsz + h];
            }
            __syncthreads();
            #pragma unroll
            for (int i = 0; i < 32; i += 8) {
                int h = h0 + ty + i, s = s0 + tx;
                if (h < Hsz) g_encT[b][h][s] = tile[tx][ty + i];
            }
        }
    }
    arrive(&g_bar0, NBLK, &g_bar0Done);
    wait_flag(&g_bar0Done);

    int tf = use_tf_p[0];

    if (bx < RBLK) {
        // ================= recurrence role: gemm + gates fused, full K =================
        float* Wt = pool;            // [24][400]  rows: c = g*8 + jj -> row g*400 + j0 + jj
        float* As = pool + 9600;     // [50][68]
        int j0 = bx * 8;
        int tjj = tid >> 5;          // 0..7, warp-uniform
        int tb  = tid & 31;          // b pair: b0 = 2*tb

        auto stage_W = [&](const float* Wsrc) {
            for (int i = tid; i < 24 * 400; i += NTHR) {
                int c = i / 400, k = i - c * 400;
                int g = c >> 3, jj = c & 7;
                Wt[i] = Wsrc[(size_t)(g * 400 + j0 + jj) * 400 + k];
            }
        };
        auto mma = [&](const float* Asrc, unsigned long long& R,
                       unsigned long long& Z, unsigned long long& N) {
            const float* wr = &Wt[(0 * 8 + tjj) * 400];
            const float* wz = &Wt[(1 * 8 + tjj) * 400];
            const float* wn = &Wt[(2 * 8 + tjj) * 400];
            for (int kt = 0; kt < 8; kt++) {
                int kbase = kt * 50;
                __syncthreads();
                for (int i = tid; i < 1600; i += NTHR) {
                    int b = i / 25, q = i - b * 25;      // coalesced over q
                    float2 v = *(const float2*)&Asrc[b * 400 + kbase + 2 * q];
                    As[(2 * q) * 68 + b]     = v.x;
                    As[(2 * q + 1) * 68 + b] = v.y;
                }
                __syncthreads();
                const float* ab = &As[2 * tb];
                #pragma unroll
                for (int k = 0; k < 50; k += 2) {
                    float2 w_r = *(const float2*)&wr[kbase + k];
                    float2 w_z = *(const float2*)&wz[kbase + k];
                    float2 w_n = *(const float2*)&wn[kbase + k];
                    float2 a0 = *(const float2*)&ab[k * 68];
                    float2 a1 = *(const float2*)&ab[(k + 1) * 68];
                    unsigned long long A0 = pk2(a0.x, a0.y);
                    unsigned long long A1 = pk2(a1.x, a1.y);
                    ffma2(R, A0, pk2(w_r.x, w_r.x)); ffma2(R, A1, pk2(w_r.y, w_r.y));
                    ffma2(Z, A0, pk2(w_z.x, w_z.x)); ffma2(Z, A1, pk2(w_z.y, w_z.y));
                    ffma2(N, A0, pk2(w_n.x, w_n.x)); ffma2(N, A1, pk2(w_n.y, w_n.y));
                }
            }
        };

        if (tf) stage_W(Whh);        // persistent across all steps
        __syncthreads();

        int j = j0 + tjj;
        float bi_r = bih[j], bi_z = bih[400 + j], bi_n = bih[800 + j];
        float bh_r = bhh[j], bh_z = bhh[400 + j], bh_n = bhh[800 + j];

        for (int t = 0; t < Lsz; t++) {
            const float* hin = (t & 1) ? g_hB : g_hA;
            float*       hout = (t & 1) ? g_hA : g_hB;
            if (t > 0) wait_flag(&g_hDone[t - 1]);
            if (!tf) {
                if (t > 0) wait_flag(&g_fusedDone[t - 1]);   // x(t) from tail(t-1)
            } else if (t >= 2) {
                wait_flag(&g_fusedDone[t - 2]);              // h-buffer reuse safety
            }

            unsigned long long R = 0, Z = 0, N = 0;
            unsigned long long iR = 0, iZ = 0, iN = 0;
            if (!tf) { __syncthreads(); stage_W(Whh); }
            mma(hin, R, Z, N);
            if (!tf) {
                __syncthreads(); stage_W(Wih);
                mma(g_x, iR, iZ, iN);
            } else {
                wait_flag(&g_batchDone[t]);
            }

            float2 R2 = up2(R), Z2 = up2(Z), N2 = up2(N);
            float gr0, gz0, gn0, gr1, gz1, gn1;
            if (tf) {
                float2 t_r = *(const float2*)&g_giBT[t][j][2 * tb];
                float2 t_z = *(const float2*)&g_giBT[t][400 + j][2 * tb];
                float2 t_n = *(const float2*)&g_giBT[t][800 + j][2 * tb];
                gr0 = t_r.x; gr1 = t_r.y;
                gz0 = t_z.x; gz1 = t_z.y;
                gn0 = t_n.x; gn1 = t_n.y;
            } else {
                float2 i_r = up2(iR), i_z = up2(iZ), i_n = up2(iN);
                gr0 = i_r.x; gr1 = i_r.y;
                gz0 = i_z.x; gz1 = i_z.y;
                gn0 = i_n.x; gn1 = i_n.y;
            }
            int b0 = 2 * tb;
            float hp0 = hin[b0 * Hsz + j];
            float hp1 = hin[(b0 + 1) * Hsz + j];
            hout[b0 * Hsz + j] = gru_h(gr0 + bi_r, R2.x + bh_r,
                                       gz0 + bi_z, Z2.x + bh_z,
                                       gn0 + bi_n, N2.x + bh_n, hp0);
            hout[(b0 + 1) * Hsz + j] = gru_h(gr1 + bi_r, R2.y + bh_r,
                                             gz1 + bi_z, Z2.y + bh_z,
                                             gn1 + bi_n, N2.y + bh_n, hp1);

            arrive(&g_hCnt[t], RBLK, &g_hDone[t]);
        }
    } else {
        // ================= fused role: batch gi, then scores + tail =================
        int fb = bx - RBLK;
        if (tf && fb < 480) {
            // batch unit fb: bt = fb/30, 40 j's
            float* As_ = pool;              // [50][68]
            float* Ws_ = pool + 3400;       // [50][44]
            int bt = fb / 30;
            int jbase = (fb % 30) * 40;
            const float* A = g_xB + (size_t)bt * Bsz * Hsz;
            int tj = tid >> 4;              // 0..15 (active < 10)
            int tb2 = tid & 15;
            int b0 = 4 * tb2, jo = 4 * tj;
            bool active = (tj < 10);
            unsigned long long acc[4][2];
            #pragma unroll
            for (int a = 0; a < 4; a++) { acc[a][0] = 0ULL; acc[a][1] = 0ULL; }

            for (int kt = 0; kt < 8; kt++) {
                int kbase = kt * 50;
                __syncthreads();
                for (int i = tid; i < 1600; i += NTHR) {
                    int b = i / 25, q = i - b * 25;
                    float2 v = *(const float2*)&A[b * Hsz + kbase + 2 * q];
                    As_[(2 * q) * 68 + b]     = v.x;
                    As_[(2 * q + 1) * 68 + b] = v.y;
                }
                for (int i = tid; i < 1000; i += NTHR) {
                    int jj = i / 25, q = i - jj * 25;
                    float2 v = *(const float2*)&Wih[(size_t)(jbase + jj) * Hsz + kbase + 2 * q];
                    Ws_[(2 * q) * 44 + jj]     = v.x;
                    Ws_[(2 * q + 1) * 44 + jj] = v.y;
                }
                __syncthreads();
                if (active) {
                    #pragma unroll 5
                    for (int k = 0; k < 50; k++) {
                        float4 av = *(const float4*)&As_[k * 68 + b0];
                        float4 wv = *(const float4*)&Ws_[k * 44 + jo];
                        unsigned long long a01 = pk2(av.x, av.y);
                        unsigned long long a23 = pk2(av.z, av.w);
                        ffma2(acc[0][0], a01, pk2(wv.x, wv.x)); ffma2(acc[0][1], a23, pk2(wv.x, wv.x));
                        ffma2(acc[1][0], a01, pk2(wv.y, wv.y)); ffma2(acc[1][1], a23, pk2(wv.y, wv.y));
                        ffma2(acc[2][0], a01, pk2(wv.z, wv.z)); ffma2(acc[2][1], a23, pk2(wv.z, wv.z));
                        ffma2(acc[3][0], a01, pk2(wv.w, wv.w)); ffma2(acc[3][1], a23, pk2(wv.w, wv.w));
                    }
                }
            }
            if (active) {
                #pragma unroll
                for (int jj = 0; jj < 4; jj++) {
                    float2 lo = up2(acc[jj][0]);
                    float2 hi = up2(acc[jj][1]);
                    *(float4*)&g_giBT[bt][jbase + jo + jj][b0] =
                        make_float4(lo.x, lo.y, hi.x, hi.y);
                }
            }
            arrive(&g_batchCnt[bt], 30, &g_batchDone[bt]);
            __syncthreads();
        }

        float* sh   = pool;                 // 64
        float* redv = pool + 64;            // 256
        int*   redi = (int*)(pool + 320);   // 256
        float* flg  = pool + 576;

        int b  = fb >> 3;
        int hc = fb & 7;
        int len = lens[b];
        __syncthreads();

        for (int t = 0; t < Lsz; t++) {
            int par = t & 1;
            if (t >= 2) wait_flag(&g_fusedDone[t - 2]);
            wait_flag(&g_hDone[t]);

            const float* hnew = (t & 1) ? g_hA : g_hB;    // hout of step t
            if (tid < HCW)
                sh[tid] = hnew[b * Hsz + hc * HCW + tid];
            __syncthreads();

            int s0 = 2 * tid;
            if (s0 < len) {
                const float* ep = &g_encT[b][hc * HCW][s0];
                float ax = 0.f, ay = 0.f;
                #pragma unroll 10
                for (int h = 0; h < HCW; h++) {
                    float hv = sh[h];
                    float2 e = *(const float2*)&ep[(size_t)h * Ssz];
                    ax += e.x * hv;
                    ay += e.y * hv;
                }
                *(float2*)&g_scpart[par][hc][b][s0] = make_float2(ax, ay);
            }

            __threadfence();
            __syncthreads();
            if (tid == 0) {
                int old = atomicAdd(&g_cnt[par][b], 1);
                flg[0] = (old == HC - 1) ? 1.f : 0.f;
            }
            __syncthreads();
            bool last = (flg[0] != 0.f);

            if (last) {
                __threadfence();
                if (tid == 0) g_cnt[par][b] = 0;

                float v[2];
                #pragma unroll
                for (int q = 0; q < 2; q++) {
                    int s = tid + NTHR * q;
                    if (s < len) {
                        float sum = 0.f;
                        #pragma unroll
                        for (int p = 0; p < HC; p++) sum += g_scpart[par][p][b][s];
                        v[q] = sum;
                    } else {
                        v[q] = -INFINITY;
                    }
                }
                float mv = v[0]; int mi = tid;
                if (v[1] > mv) { mv = v[1]; mi = tid + NTHR; }
                redv[tid] = mv;
                redi[tid] = mi;
                __syncthreads();
                for (int st = 128; st > 0; st >>= 1) {
                    if (tid < st) {
                        float w2 = redv[tid + st];
                        int   i2 = redi[tid + st];
                        if (w2 > redv[tid] || (w2 == redv[tid] && i2 < redi[tid])) {
                            redv[tid] = w2;
                            redi[tid] = i2;
                        }
                    }
                    __syncthreads();
                }
                float m = redv[0];
                int amax = redi[0];
                __syncthreads();

                float e0 = expf(v[0] - m);
                float e1 = expf(v[1] - m);
                redv[tid] = e0 + e1;
                __syncthreads();
                for (int st = 128; st > 0; st >>= 1) {
                    if (tid < st) redv[tid] += redv[tid + st];
                    __syncthreads();
                }
                float inv = 1.f / redv[0];

                float* orow = out + (size_t)b * Lsz * Vsz + (size_t)t * Vsz;
                if (tid < len)
                    atomicAdd(&orow[uttrs[b * Ssz + tid]], e0 * inv);
                if (tid + NTHR < len)
                    atomicAdd(&orow[uttrs[b * Ssz + tid + NTHR]], e1 * inv);

                if (tid == 0) {
                    int pred = uttrs[b * Ssz + amax];
                    if (write_preds)
                        out[(size_t)Bsz * Lsz * Vsz + (size_t)t * Bsz + b] = (float)pred;
                    ((int*)flg)[1] = tf ? targets[b * Lsz + t] : pred;
                }
                __syncthreads();
                if (!tf) {
                    int nxt = ((int*)flg)[1];
                    if (tid < 100)
                        ((float4*)(g_x + b * Hsz))[tid] =
                            ((const float4*)(emb + (size_t)nxt * Hsz))[tid];
                }
            }

            arrive(&g_fusedCnt[t], FBLK, &g_fusedDone[t]);

            // lazy zero of row (b, t+1): ordered before tail(t+1) via cnt fence chain
            if (t + 1 < Lsz) {
                float* row = out + (size_t)b * Lsz * Vsz + (size_t)(t + 1) * Vsz;
                for (int i = hc * NTHR + tid; i < Vsz / 4; i += HC * NTHR) {
                    float4* p = (float4*)row + i;
                    asm volatile("st.global.cs.v4.f32 [%0], {%1, %2, %3, %4};"
                                 :: "l"(p), "f"(0.f), "f"(0.f), "f"(0.f), "f"(0.f) : "memory");
                }
            }
        }
    }
}

// ---------------- launch ----------------
extern "C" void kernel_launch(void* const* d_in, const int* in_sizes, int n_in,
                              void* d_out, int out_size) {
    const float* eh       = (const float*)d_in[0];
    const float* enc      = (const float*)d_in[1];
    const int*   lens     = (const int*)d_in[2];
    const int*   uttrs    = (const int*)d_in[3];
    const int*   targets  = (const int*)d_in[4];
    const int*   slot     = (const int*)d_in[5];
    const int*   use_tf   = (const int*)d_in[6];
    const float* emb      = (const float*)d_in[7];
    const float* slot_emb = (const float*)d_in[8];
    const float* Wih      = (const float*)d_in[9];
    const float* Whh      = (const float*)d_in[10];
    const float* bih      = (const float*)d_in[11];
    const float* bhh      = (const float*)d_in[12];
    float* out = (float*)d_out;

    cudaFuncSetAttribute(persist_kernel,
                         cudaFuncAttributeMaxDynamicSharedMemorySize, SMEM_BYTES);

    int write_preds = out_size > Bsz * Lsz * Vsz;
    reset_kernel<<<1, 128>>>();
    persist_kernel<<<NBLK, NTHR, SMEM_BYTES>>>(eh, enc, lens, uttrs, targets, slot, use_tf,
                                               emb, slot_emb, Wih, Whh, bih, bhh,
                                               out, out_size, write_preds);
}

// round 11
// speedup vs baseline: 1.2361x; 1.2361x over previous
#include <cuda_runtime.h>
#include <math.h>

#define Bsz 64
#define Ssz 512
#define Hsz 400
#define Vsz 32000
#define Lsz 16
#define NPART 8
#define KC   50
#define JT   24
#define HC   8
#define HCW  50
#define NBLK 912          // 400 gemm-role + 512 fused-role
#define NTHR 128
#define GEMM_BLOCKS 400

// ---------------- device globals ----------------
__device__ float g_Gpart[NPART][Bsz][2400];
__device__ float g_hA[Bsz * Hsz];
__device__ float g_hB[Bsz * Hsz];
__device__ float g_x[Bsz * Hsz];
__device__ float g_xB[Lsz * Bsz * Hsz];
__device__ float g_giB[Lsz][Bsz][1200];
__device__ float g_encT[Bsz][Hsz][Ssz];
__device__ float g_scpart[2][HC][Bsz][Ssz];
__device__ int   g_cnt[2][Bsz];
// hierarchical rendezvous state: sub-counters on distinct 256B-strided lines
__device__ int   g_subGemm[Lsz][25 * 64];   // 400 arrivers: 25 groups of 16
__device__ int   g_subH[Lsz][32 * 64];      // 512 arrivers: 32 groups of 16
__device__ int   g_subF[Lsz][32 * 64];      // 512 arrivers: 32 groups of 16
__device__ int   g_subBar[2][38 * 64];      // 912 arrivers: 38 groups of 24
__device__ int   g_gemmCnt[Lsz],  g_gemmDone[Lsz];
__device__ int   g_hCnt[Lsz],     g_hDone[Lsz];
__device__ int   g_fusedCnt[Lsz], g_fusedDone[Lsz];
__device__ int   g_batchCnt[Lsz], g_batchDone[Lsz];   // 30 arrivers: flat is fine
__device__ int   g_bar[2], g_barDone[2];

// ---------------- f32x2 helpers ----------------
__device__ __forceinline__ unsigned long long pk2(float x, float y) {
    unsigned long long r;
    asm("mov.b64 %0, {%1, %2};" : "=l"(r) : "f"(x), "f"(y));
    return r;
}
__device__ __forceinline__ void ffma2(unsigned long long& d,
                                      unsigned long long a, unsigned long long b) {
    asm("fma.rn.f32x2 %0, %1, %2, %0;" : "+l"(d) : "l"(a), "l"(b));
}
__device__ __forceinline__ float2 up2(unsigned long long v) {
    float2 f;
    asm("mov.b64 {%0, %1}, %2;" : "=f"(f.x), "=f"(f.y) : "l"(v));
    return f;
}

// ---------------- sync primitives ----------------
__device__ __forceinline__ void wait_flag(int* flag) {
    if (threadIdx.x == 0) {
        int v;
        while (true) {
            asm volatile("ld.acquire.gpu.b32 %0, [%1];" : "=r"(v) : "l"(flag) : "memory");
            if (v) break;
            __nanosleep(32);
        }
    }
    __syncthreads();
}
// two-level arrive: sub-group atomic on a private line, last-in-group escalates
__device__ __forceinline__ void arrive_h(int* subs, int subIdx, int subTarget,
                                         int* root, int rootTarget, int* flag) {
    __threadfence();
    __syncthreads();
    if (threadIdx.x == 0) {
        int old = atomicAdd(&subs[subIdx * 64], 1);
        if (old == subTarget - 1) {
            int r = atomicAdd(root, 1);
            if (r == rootTarget - 1)
                asm volatile("st.release.gpu.b32 [%0], %1;" :: "l"(flag), "r"(1) : "memory");
        }
    }
}
__device__ __forceinline__ void arrive_flat(int* cnt, int target, int* flag) {
    __threadfence();
    __syncthreads();
    if (threadIdx.x == 0) {
        int old = atomicAdd(cnt, 1);
        if (old == target - 1)
            asm volatile("st.release.gpu.b32 [%0], %1;" :: "l"(flag), "r"(1) : "memory");
    }
}

// ---------------- reset counters/flags each replay ----------------
__global__ __launch_bounds__(256) void reset_kernel() {
    int i = threadIdx.x;
    if (i < Lsz) {
        g_gemmCnt[i] = 0; g_gemmDone[i] = 0;
        g_hCnt[i] = 0;    g_hDone[i] = 0;
        g_fusedCnt[i] = 0; g_fusedDone[i] = 0;
        g_batchCnt[i] = 0; g_batchDone[i] = 0;
    }
    if (i < 2) { g_bar[i] = 0; g_barDone[i] = 0; }
    if (i < Bsz) { g_cnt[0][i] = 0; g_cnt[1][i] = 0; }
    for (int k = i; k < Lsz * 25; k += 256) g_subGemm[k / 25][(k % 25) * 64] = 0;
    for (int k = i; k < Lsz * 32; k += 256) g_subH[k / 32][(k % 32) * 64] = 0;
    for (int k = i; k < Lsz * 32; k += 256) g_subF[k / 32][(k % 32) * 64] = 0;
    for (int k = i; k < 2 * 38; k += 256)   g_subBar[k / 38][(k % 38) * 64] = 0;
}

// ---------------- the persistent kernel ----------------
__global__ __launch_bounds__(NTHR, 8) void persist_kernel(
    const float* __restrict__ eh,
    const float* __restrict__ enc,
    const int* __restrict__ lens,
    const int* __restrict__ uttrs,
    const int* __restrict__ targets,
    const int* __restrict__ slot_p,
    const int* __restrict__ use_tf_p,
    const float* __restrict__ emb,
    const float* __restrict__ slot_emb,
    const float* __restrict__ Wih,
    const float* __restrict__ Whh,
    const float* __restrict__ bih,
    const float* __restrict__ bhh,
    float* __restrict__ out,
    int out_size, int write_preds)
{
    __shared__ float pool[6700];   // 26.8 KB (8 blocks/SM)

    int bx = blockIdx.x;
    int tid = threadIdx.x;
    int gidx = bx * NTHR + tid;
    const int nt = NBLK * NTHR;

    // ============ Phase 0: zero t=0 rows + pad, init, xbuild ============
    {
        for (int i = gidx; i < Bsz * (Vsz / 4); i += nt) {
            int b = i / (Vsz / 4), q = i % (Vsz / 4);
            float4* p = (float4*)(out + (size_t)b * Lsz * Vsz) + q;
            asm volatile("st.global.cs.v4.f32 [%0], {%1, %2, %3, %4};"
                         :: "l"(p), "f"(0.f), "f"(0.f), "f"(0.f), "f"(0.f) : "memory");
        }
        for (int i = (Bsz * Lsz * Vsz) + gidx; i < out_size; i += nt)
            asm volatile("st.global.cs.f32 [%0], %1;" :: "l"(out + i), "f"(0.f) : "memory");

        int slot = slot_p[0];
        for (int i = gidx; i < Bsz * Hsz; i += nt) {
            g_hA[i] = eh[i];
            g_x[i] = slot_emb[slot * Hsz + i % Hsz];
        }
        for (int i = gidx; i < Lsz * Bsz * 100; i += nt) {
            int row = i / 100, q = i % 100;
            int t = row >> 6, b = row & 63;
            const float* src = (t == 0) ? (slot_emb + slot * Hsz)
                                        : (emb + (size_t)targets[b * Lsz + (t - 1)] * Hsz);
            ((float4*)(g_xB + (size_t)row * Hsz))[q] = ((const float4*)src)[q];
        }
    }
    arrive_h(g_subBar[0], bx % 38, 24, &g_bar[0], 38, &g_barDone[0]);
    wait_flag(&g_barDone[0]);

    // ============ Phase 1: batch gi GEMM (0..479) || transpose (480..911) ============
    if (bx < 480) {
        float (*As)[68] = (float(*)[68])pool;              // 50 x 68
        float (*Ws)[44] = (float(*)[44])(pool + 3400);     // 50 x 44
        int bt = bx / 30;
        int jbase = (bx % 30) * 40;
        const float* A = g_xB + (size_t)bt * Bsz * Hsz;

        int tj = tid / 8;      // 0..15 (only 0..9 compute)
        int tb = tid % 8;
        int b0 = 8 * tb;
        int j0 = 4 * tj;
        bool active = (tj < 10);

        unsigned long long acc[4][4];
        #pragma unroll
        for (int j = 0; j < 4; j++)
            #pragma unroll
            for (int p = 0; p < 4; p++) acc[j][p] = 0ULL;

        for (int kt = 0; kt < 8; kt++) {
            int kbase = kt * KC;
            __syncthreads();
            for (int i = tid; i < 1600; i += NTHR) {
                int q = i >> 6, b = i & 63;
                float2 v = *(const float2*)&A[b * Hsz + kbase + 2 * q];
                As[2 * q + 0][b] = v.x;
                As[2 * q + 1][b] = v.y;
            }
            for (int i = tid; i < 1000; i += NTHR) {
                int q = i / 40, j = i % 40;
                float2 v = *(const float2*)&Wih[(size_t)(jbase + j) * Hsz + kbase + 2 * q];
                Ws[2 * q + 0][j] = v.x;
                Ws[2 * q + 1][j] = v.y;
            }
            __syncthreads();
            if (active) {
                #pragma unroll 5
                for (int k = 0; k < KC; k++) {
                    float4 av0 = *(const float4*)&As[k][b0];
                    float4 av1 = *(const float4*)&As[k][b0 + 4];
                    float4 wv  = *(const float4*)&Ws[k][j0];
                    unsigned long long a01 = pk2(av0.x, av0.y);
                    unsigned long long a23 = pk2(av0.z, av0.w);
                    unsigned long long a45 = pk2(av1.x, av1.y);
                    unsigned long long a67 = pk2(av1.z, av1.w);
                    unsigned long long w0 = pk2(wv.x, wv.x);
                    unsigned long long w1 = pk2(wv.y, wv.y);
                    unsigned long long w2 = pk2(wv.z, wv.z);
                    unsigned long long w3 = pk2(wv.w, wv.w);
                    ffma2(acc[0][0], a01, w0); ffma2(acc[0][1], a23, w0);
                    ffma2(acc[0][2], a45, w0); ffma2(acc[0][3], a67, w0);
                    ffma2(acc[1][0], a01, w1); ffma2(acc[1][1], a23, w1);
                    ffma2(acc[1][2], a45, w1); ffma2(acc[1][3], a67, w1);
                    ffma2(acc[2][0], a01, w2); ffma2(acc[2][1], a23, w2);
                    ffma2(acc[2][2], a45, w2); ffma2(acc[2][3], a67, w2);
                    ffma2(acc[3][0], a01, w3); ffma2(acc[3][1], a23, w3);
                    ffma2(acc[3][2], a45, w3); ffma2(acc[3][3], a67, w3);
                }
            }
        }
        if (active) {
            #pragma unroll
            for (int p = 0; p < 4; p++) {
                float2 f0 = up2(acc[0][p]);
                float2 f1 = up2(acc[1][p]);
                float2 f2 = up2(acc[2][p]);
                float2 f3 = up2(acc[3][p]);
                *(float4*)&g_giB[bt][b0 + 2 * p][jbase + j0]     = make_float4(f0.x, f1.x, f2.x, f3.x);
                *(float4*)&g_giB[bt][b0 + 2 * p + 1][jbase + j0] = make_float4(f0.y, f1.y, f2.y, f3.y);
            }
        }
    } else {
        // transpose enc[b][s][h] -> encT[b][h][s]
        float (*tile)[33] = (float(*)[33])pool;
        int tx = tid & 31, ty = tid >> 5;    // 32 x 4
        for (int tt = bx - 480; tt < Bsz * 16 * 13; tt += NBLK - 480) {
            int b = tt / (16 * 13);
            int rem = tt % (16 * 13);
            int s0 = (rem / 13) * 32;
            int h0 = (rem % 13) * 32;
            __syncthreads();
            #pragma unroll
            for (int i = 0; i < 32; i += 4) {
                int s = s0 + ty + i, h = h0 + tx;
                if (h < Hsz) tile[ty + i][tx] = enc[((size_t)b * Ssz + s) * Hsz + h];
            }
            __syncthreads();
            #pragma unroll
            for (int i = 0; i < 32; i += 4) {
                int h = h0 + ty + i, s = s0 + tx;
                if (h < Hsz) g_encT[b][h][s] = tile[tx][ty + i];
            }
        }
    }
    arrive_h(g_subBar[1], bx % 38, 24, &g_bar[1], 38, &g_barDone[1]);
    wait_flag(&g_barDone[1]);

    int tf = use_tf_p[0];

    // ============ Phase 2: the 16-step recurrence ============
    if (bx < GEMM_BLOCKS) {
        // -------- GEMM role: W tiles persist in smem --------
        float (*As)[68]  = (float(*)[68])pool;              // 3400
        float (*WhS)[28] = (float(*)[28])(pool + 3400);     // 1400
        float (*WiS)[28] = (float(*)[28])(pool + 4800);     // 1400
        int jt = bx >> 3, ks = bx & 7;
        int jbase = jt * JT;
        int kbase = ks * KC;
        int tj = tid / 16, tb = tid % 16;
        int b0 = 4 * tb, j0 = 4 * tj;
        bool active = (tj < 6);

        __syncthreads();
        for (int i = tid; i < 600; i += NTHR) {
            int q = i / JT, j = i % JT;
            float2 v = *(const float2*)&Whh[(size_t)(jbase + j) * Hsz + kbase + 2 * q];
            WhS[2 * q + 0][j] = v.x;
            WhS[2 * q + 1][j] = v.y;
        }
        if (!tf) {
            for (int i = tid; i < 600; i += NTHR) {
                int q = i / JT, j = i % JT;
                float2 v = *(const float2*)&Wih[(size_t)(jbase + j) * Hsz + kbase + 2 * q];
                WiS[2 * q + 0][j] = v.x;
                WiS[2 * q + 1][j] = v.y;
            }
        }
        __syncthreads();

        for (int t = 0; t < Lsz; t++) {
            if (t > 0)
                wait_flag(tf ? &g_hDone[t - 1] : &g_fusedDone[t - 1]);
            const float* hin = (t & 1) ? g_hB : g_hA;
            for (int mat = tf ? 1 : 0; mat < 2; mat++) {
                const float* A = mat ? hin : g_x;
                float (*Ws)[28] = mat ? WhS : WiS;
                __syncthreads();
                for (int i = tid; i < 1600; i += NTHR) {
                    int q = i >> 6, b = i & 63;
                    float2 v = *(const float2*)&A[b * Hsz + kbase + 2 * q];
                    As[2 * q + 0][b] = v.x;
                    As[2 * q + 1][b] = v.y;
                }
                __syncthreads();
                if (active) {
                    unsigned long long acc[4][2];
                    #pragma unroll
                    for (int jj = 0; jj < 4; jj++) { acc[jj][0] = 0ULL; acc[jj][1] = 0ULL; }
                    #pragma unroll 5
                    for (int k = 0; k < KC; k++) {
                        float4 av = *(const float4*)&As[k][b0];
                        float4 wv = *(const float4*)&Ws[k][j0];
                        unsigned long long a01 = pk2(av.x, av.y);
                        unsigned long long a23 = pk2(av.z, av.w);
                        unsigned long long w0 = pk2(wv.x, wv.x);
                        unsigned long long w1 = pk2(wv.y, wv.y);
                        unsigned long long w2 = pk2(wv.z, wv.z);
                        unsigned long long w3 = pk2(wv.w, wv.w);
                        ffma2(acc[0][0], a01, w0); ffma2(acc[0][1], a23, w0);
                        ffma2(acc[1][0], a01, w1); ffma2(acc[1][1], a23, w1);
                        ffma2(acc[2][0], a01, w2); ffma2(acc[2][1], a23, w2);
                        ffma2(acc[3][0], a01, w3); ffma2(acc[3][1], a23, w3);
                    }
                    int obase = mat * 1200 + jbase + j0;
                    #pragma unroll
                    for (int bb = 0; bb < 4; bb++) {
                        float v0 = (bb & 1) ? up2(acc[0][bb >> 1]).y : up2(acc[0][bb >> 1]).x;
                        float v1 = (bb & 1) ? up2(acc[1][bb >> 1]).y : up2(acc[1][bb >> 1]).x;
                        float v2 = (bb & 1) ? up2(acc[2][bb >> 1]).y : up2(acc[2][bb >> 1]).x;
                        float v3 = (bb & 1) ? up2(acc[3][bb >> 1]).y : up2(acc[3][bb >> 1]).x;
                        *(float4*)&g_Gpart[ks][b0 + bb][obase] = make_float4(v0, v1, v2, v3);
                    }
                }
            }
            arrive_h(g_subGemm[t], bx % 25, 16, &g_gemmCnt[t], 25, &g_gemmDone[t]);
        }
    } else {
        // -------- fused role: gates + lazy zero + scores + tail --------
        float* sh   = pool;                 // 64
        float* redv = pool + 64;            // 128
        int*   redi = (int*)(pool + 192);   // 128
        float* flg  = pool + 320;

        int fb = bx - GEMM_BLOCKS;
        int b  = fb >> 3;
        int hc = fb & 7;
        int len = lens[b];
        int sub = fb & 31;

        for (int t = 0; t < Lsz; t++) {
            int par = t & 1;
            if (t >= 2) wait_flag(&g_fusedDone[t - 2]);
            wait_flag(&g_gemmDone[t]);

            const float* hin  = (t & 1) ? g_hB : g_hA;
            float*       hout = (t & 1) ? g_hA : g_hB;

            // gates for h in [hc*50, hc*50+50)
            if (tid < HCW) {
                int j = hc * HCW + tid;
                float ir = bih[j], iz = bih[400 + j], in_ = bih[800 + j];
                float hr = bhh[j], hz = bhh[400 + j], hn = bhh[800 + j];
                if (tf) {
                    ir += g_giB[t][b][j];
                    iz += g_giB[t][b][400 + j];
                    in_ += g_giB[t][b][800 + j];
                    #pragma unroll
                    for (int p = 0; p < NPART; p++) {
                        const float* P = &g_Gpart[p][b][0];
                        hr += P[1200 + j]; hz += P[1600 + j]; hn += P[2000 + j];
                    }
                } else {
                    #pragma unroll
                    for (int p = 0; p < NPART; p++) {
                        const float* P = &g_Gpart[p][b][0];
                        ir += P[j];        iz += P[400 + j];  in_ += P[800 + j];
                        hr += P[1200 + j]; hz += P[1600 + j]; hn += P[2000 + j];
                    }
                }
                float r = 1.f / (1.f + expf(-(ir + hr)));
                float z = 1.f / (1.f + expf(-(iz + hz)));
                float n = tanhf(in_ + r * hn);
                float hnew = (1.f - z) * n + z * hin[b * Hsz + j];
                sh[tid] = hnew;
                hout[b * Hsz + j] = hnew;
            }
            arrive_h(g_subH[t], sub, 16, &g_hCnt[t], 32, &g_hDone[t]);

            // lazy zero of row (b, t+1)
            if (t + 1 < Lsz) {
                float* row = out + (size_t)b * Lsz * Vsz + (size_t)(t + 1) * Vsz;
                for (int i = hc * NTHR + tid; i < Vsz / 4; i += HC * NTHR) {
                    float4* p = (float4*)row + i;
                    asm volatile("st.global.cs.v4.f32 [%0], {%1, %2, %3, %4};"
                                 :: "l"(p), "f"(0.f), "f"(0.f), "f"(0.f), "f"(0.f) : "memory");
                }
            }

            // partial scores: thread owns 4 s, broadcast-MAC over 50 h
            int s0 = 4 * tid;
            if (s0 < len) {
                const float4* ep = (const float4*)&g_encT[b][hc * HCW][0] + tid;
                float4 acc = make_float4(0.f, 0.f, 0.f, 0.f);
                #pragma unroll 10
                for (int h = 0; h < HCW; h++) {
                    float hv = sh[h];
                    float4 e = ep[(size_t)h * 128];
                    acc.x += e.x * hv; acc.y += e.y * hv;
                    acc.z += e.z * hv; acc.w += e.w * hv;
                }
                *(float4*)&g_scpart[par][hc][b][s0] = acc;
            }

            // per-b arrival (8 arrivers on distinct addresses — already cheap)
            __threadfence();
            __syncthreads();
            if (tid == 0) {
                int old = atomicAdd(&g_cnt[par][b], 1);
                flg[0] = (old == HC - 1) ? 1.f : 0.f;
            }
            __syncthreads();
            bool last = (flg[0] != 0.f);
            if (!last) {
                arrive_h(g_subF[t], sub, 16, &g_fusedCnt[t], 32, &g_fusedDone[t]);
                continue;
            }

            // ---- tail: softmax + scatter + pred + next x ----
            __threadfence();
            if (tid == 0) g_cnt[par][b] = 0;

            float v[4];
            #pragma unroll
            for (int q = 0; q < 4; q++) {
                int s = tid + 128 * q;
                if (s < len) {
                    float sum = 0.f;
                    #pragma unroll
                    for (int p = 0; p < HC; p++) sum += g_scpart[par][p][b][s];
                    v[q] = sum;
                } else {
                    v[q] = -INFINITY;
                }
            }
            float mv = v[0]; int mi = tid;
            #pragma unroll
            for (int q = 1; q < 4; q++)
                if (v[q] > mv) { mv = v[q]; mi = tid + 128 * q; }
            redv[tid] = mv;
            redi[tid] = mi;
            __syncthreads();
            for (int st = 64; st > 0; st >>= 1) {
                if (tid < st) {
                    float w2 = redv[tid + st];
                    int   i2 = redi[tid + st];
                    if (w2 > redv[tid] || (w2 == redv[tid] && i2 < redi[tid])) {
                        redv[tid] = w2;
                        redi[tid] = i2;
                    }
                }
                __syncthreads();
            }
            float m = redv[0];
            int amax = redi[0];
            __syncthreads();

            float e[4], lsum = 0.f;
            #pragma unroll
            for (int q = 0; q < 4; q++) {
                e[q] = expf(v[q] - m);
                lsum += e[q];
            }
            redv[tid] = lsum;
            __syncthreads();
            for (int st = 64; st > 0; st >>= 1) {
                if (tid < st) redv[tid] += redv[tid + st];
                __syncthreads();
            }
            float inv = 1.f / redv[0];

            float* orow = out + (size_t)b * Lsz * Vsz + (size_t)t * Vsz;
            #pragma unroll
            for (int q = 0; q < 4; q++) {
                int s = tid + 128 * q;
                if (s < len)
                    atomicAdd(&orow[uttrs[b * Ssz + s]], e[q] * inv);
            }

            if (tid == 0) {
                int pred = uttrs[b * Ssz + amax];
                if (write_preds)
                    out[(size_t)Bsz * Lsz * Vsz + (size_t)t * Bsz + b] = (float)pred;
                ((int*)flg)[1] = tf ? targets[b * Lsz + t] : pred;
            }
            __syncthreads();
            {
                int nxt = ((int*)flg)[1];
                if (tid < 100)
                    ((float4*)(g_x + b * Hsz))[tid] =
                        ((const float4*)(emb + (size_t)nxt * Hsz))[tid];
            }

            arrive_h(g_subF[t], sub, 16, &g_fusedCnt[t], 32, &g_fusedDone[t]);
        }
    }
}

// ---------------- launch ----------------
extern "C" void kernel_launch(void* const* d_in, const int* in_sizes, int n_in,
                              void* d_out, int out_size) {
    const float* eh       = (const float*)d_in[0];
    const float* enc      = (const float*)d_in[1];
    const int*   lens     = (const int*)d_in[2];
    const int*   uttrs    = (const int*)d_in[3];
    const int*   targets  = (const int*)d_in[4];
    const int*   slot     = (const int*)d_in[5];
    const int*   use_tf   = (const int*)d_in[6];
    const float* emb      = (const float*)d_in[7];
    const float* slot_emb = (const float*)d_in[8];
    const float* Wih      = (const float*)d_in[9];
    const float* Whh      = (const float*)d_in[10];
    const float* bih      = (const float*)d_in[11];
    const float* bhh      = (const float*)d_in[12];
    float* out = (float*)d_out;

    int write_preds = out_size > Bsz * Lsz * Vsz;
    reset_kernel<<<1, 256>>>();
    persist_kernel<<<NBLK, NTHR>>>(eh, enc, lens, uttrs, targets, slot, use_tf,
                                   emb, slot_emb, Wih, Whh, bih, bhh,
                                   out, out_size, write_preds);
}